// round 7
// baseline (speedup 1.0000x reference)
#include <cuda_runtime.h>
#include <math.h>

#define BB  8
#define LL  512
#define KK  16
#define EE  32
#define NHH 64
#define GG  192
#define CH      16           // GRU: steps per GI prefetch chunk
#define NCHUNK  (LL/CH)      // 32

// -------- scratch (static device globals; no runtime allocation) --------
__device__ float g_q[BB*LL*EE];
__device__ float g_k[BB*LL*EE];
__device__ int   g_bcnt[BB*KK];
__device__ int   g_boff[BB*KK];
__device__ int   g_bidxC[BB*LL];     // compacted buckets, per-b 512 entries
__device__ float g_M2[GG*KK];        // W_ih @ Wo   (192 x 16)
__device__ float g_cc[GG];           // W_ih @ bo + b_ih + b_hh
__device__ float g_GI[BB*LL*GG];     // precomputed input gates (biases folded)

__device__ __forceinline__ float tanh_fast(float x) {
    float y;
    asm("tanh.approx.f32 %0, %1;" : "=f"(y) : "f"(x));
    return y;
}
#define FMA2(acc, x, y) \
    asm("fma.rn.f32x2 %0, %1, %2, %0;" : "+l"(acc) : "l"(x), "l"(y))
__device__ __forceinline__ float f2lo(unsigned long long v) {
    return __uint_as_float((unsigned)v);
}
__device__ __forceinline__ float f2hi(unsigned long long v) {
    return __uint_as_float((unsigned)(v >> 32));
}

// -------- kernel 1: setup (proj blocks 0-31, fold block 32, buckets 33-40) --
__global__ void __launch_bounds__(512) k_setup(
        const float* __restrict__ ts,
        const float* __restrict__ Wl, const float* __restrict__ bl,
        const float* __restrict__ Wp, const float* __restrict__ bp,
        const float* __restrict__ Wq, const float* __restrict__ bq,
        const float* __restrict__ Wk, const float* __restrict__ bk,
        const float* __restrict__ W_ih, const float* __restrict__ Wo,
        const float* __restrict__ b_ih, const float* __restrict__ bo,
        const float* __restrict__ b_hh,
        const int*   __restrict__ mark, const float* __restrict__ npm) {
    int blk = blockIdx.x, tid = threadIdx.x;
    if (blk < 32) {
        __shared__ float ke_s[128*33];
        __shared__ float wq_s[EE*33], wk_s[EE*33];
        __shared__ float sWp[EE], sbp[EE];
        __shared__ float sWl, sbl;
        int b = blk >> 2, rbase = (blk & 3) * 128;

        for (int i = tid; i < EE*EE; i += 512) {
            int e = i >> 5, j = i & 31;
            wq_s[e*33+j] = Wq[i];
            wk_s[e*33+j] = Wk[i];
        }
        if (tid < EE-1) { sWp[tid] = Wp[tid]; sbp[tid] = bp[tid]; }
        if (tid == 0)   { sWl = Wl[0]; sbl = bl[0]; }
        __syncthreads();

        for (int idx = tid; idx < 128*EE; idx += 512) {
            int r = idx >> 5, i = idx & 31;
            float t = ts[b*LL + rbase + r];
            float v = (i == 0) ? fmaf(t, sWl, sbl)
                               : __sinf(fmaf(t, sWp[i-1], sbp[i-1]));
            ke_s[r*33 + i] = v;
        }
        __syncthreads();

        int e = tid & 31, r0 = tid >> 5;   // warp <-> one r0 (ke reads uniform)
        float wq[EE], wk[EE];
        #pragma unroll
        for (int j = 0; j < EE; j++) { wq[j] = wq_s[e*33+j]; wk[j] = wk_s[e*33+j]; }
        float bqv = __ldg(&bq[e]), bkv = __ldg(&bk[e]);
        #pragma unroll
        for (int pass = 0; pass < 8; pass++) {
            int r = pass*16 + r0;
            float aq = bqv, ak = bkv;
            #pragma unroll
            for (int j = 0; j < EE; j++) {
                float kv = ke_s[r*33+j];
                aq = fmaf(wq[j], kv, aq);
                ak = fmaf(wk[j], kv, ak);
            }
            int row = b*LL + rbase + r;
            g_q[row*EE + e] = aq;
            g_k[row*EE + e] = ak;
        }
    } else if (blk == 32) {
        // ---- fold: M2 = W_ih@Wo, cc = W_ih@bo + b_ih + b_hh ----
        if (tid < GG) {
            int g = tid;
            float wrow[NHH];
            #pragma unroll
            for (int o = 0; o < NHH; o++) wrow[o] = W_ih[g*NHH+o];
            float cc = b_ih[g] + b_hh[g];
            #pragma unroll
            for (int o = 0; o < NHH; o++) cc += wrow[o] * bo[o];
            g_cc[g] = cc;
            for (int c = 0; c < KK; c++) {
                float a = 0.f;
                #pragma unroll
                for (int o = 0; o < NHH; o++) a += wrow[o] * Wo[o*KK+c];
                g_M2[g*KK+c] = a;
            }
        }
    } else {
        // ---- compacted bucket build: warp per category + block scan ----
        __shared__ int cnt_sh[KK], off_sh[KK];
        int b = blk - 33;
        int c = tid >> 5, lane = tid & 31;    // 16 warps = 16 categories
        unsigned mrec[LL/32];
        int cnt = 0;
        #pragma unroll
        for (int ch = 0; ch < LL/32; ch++) {
            int k = ch*32 + lane;
            int   mk = mark[b*LL+k];
            float np = npm[b*LL+k];
            bool hit = (mk == c+1) && (np > 0.f);
            unsigned m = __ballot_sync(0xffffffffu, hit);
            mrec[ch] = m;
            cnt += __popc(m);
        }
        if (lane == 0) cnt_sh[c] = cnt;
        __syncthreads();
        if (tid == 0) {
            int acc = 0;
            #pragma unroll
            for (int i = 0; i < KK; i++) { off_sh[i] = acc; acc += cnt_sh[i]; }
        }
        __syncthreads();
        int off = off_sh[c], pos = 0;
        #pragma unroll
        for (int ch = 0; ch < LL/32; ch++) {
            unsigned m = mrec[ch];
            if ((m >> lane) & 1u)
                g_bidxC[b*LL + off + pos + __popc(m & ((1u<<lane)-1u))] = ch*32 + lane;
            pos += __popc(m);
        }
        if (lane == 0) { g_bcnt[b*KK+c] = cnt; g_boff[b*KK+c] = off; }
    }
}

// -------- kernel 2: fused scores + bucketed softmax + GI --------
// smem layout (floats):
#define SOFF_S    0                       // 32*512 score tile
#define SOFF_KB   16384                   // 64*36  k staging (stride 36)
#define SOFF_VAL  (16384+2304)            // 512
#define SOFF_X    (SOFF_VAL+512)          // 512
#define SOFF_M2   (SOFF_X+512)            // 192*17
#define SOFF_CC   (SOFF_M2+3264)          // 192
#define SOFF_INT  (SOFF_CC+192)           // ints: cnt 16, off 16, bidx 512
#define SMEM_ATT_BYTES ((SOFF_INT + 544) * 4)

__global__ void __launch_bounds__(512) k_att2(const float* __restrict__ val) {
    extern __shared__ float sm[];
    float* S_s   = sm + SOFF_S;
    float* kbuf  = sm + SOFF_KB;
    float* val_s = sm + SOFF_VAL;
    float* x_s   = sm + SOFF_X;
    float* M2_s  = sm + SOFF_M2;
    float* cc_s  = sm + SOFF_CC;
    int*   cnt_s  = (int*)(sm + SOFF_INT);
    int*   off_s  = cnt_s + KK;
    int*   bidx_s = off_s + KK;

    int tid = threadIdx.x;                 // 512 threads = 16 warps
    int b = blockIdx.y;
    int qbase = blockIdx.x * 32;

    if (tid < LL) val_s[tid] = val[b*LL+tid];
    if (tid < KK) { cnt_s[tid] = g_bcnt[b*KK+tid]; off_s[tid] = g_boff[b*KK+tid]; }
    if (tid >= 512-LL) { /* placeholder keeps warps busy-free */ }
    if (tid < LL) bidx_s[tid] = g_bidxC[b*LL+tid];
    for (int i = tid; i < GG*KK; i += 512) {
        int g = i >> 4, c = i & 15;
        M2_s[g*17+c] = g_M2[i];
    }
    if (tid < GG) cc_s[tid] = g_cc[tid];

    // ---- phase 1: S_tile[32][512] = q_tile @ k^T / sqrt(32) ----
    int ql4 = tid >> 4, kg = tid & 15;
    // q row in registers, packed f32x2 (16 x u64)
    unsigned long long q2[16];
    {
        const ulonglong2* qp = (const ulonglong2*)(g_q + (size_t)(b*LL + qbase + ql4)*EE);
        #pragma unroll
        for (int i = 0; i < 8; i++) {
            ulonglong2 v = qp[i];
            q2[2*i] = v.x; q2[2*i+1] = v.y;
        }
    }
    unsigned kaddr = (unsigned)__cvta_generic_to_shared(kbuf);
    const float sc = 0.17677669529663687f; // 1/sqrt(32)
    for (int kt = 0; kt < 8; kt++) {
        __syncthreads();
        {   // stage 64x32 k-block: one LDG.128 + STS.128 per thread
            int r = tid >> 3, e4 = (tid & 7) * 4;
            float4 v = *(const float4*)(g_k + (size_t)(b*LL + kt*64 + r)*EE + e4);
            *(float4*)&kbuf[r*36 + e4] = v;
        }
        __syncthreads();
        unsigned long long a0=0ull, a1=0ull, a2=0ull, a3=0ull;
        #pragma unroll
        for (int j = 0; j < 8; j++) {
            unsigned long long hx, hy;
            unsigned base = kaddr + (unsigned)(((kg*4)*36 + j*4) * 4);
            asm volatile("ld.shared.v2.u64 {%0, %1}, [%2];"
                         : "=l"(hx), "=l"(hy) : "r"(base));
            FMA2(a0, q2[2*j], hx); FMA2(a0, q2[2*j+1], hy);
            asm volatile("ld.shared.v2.u64 {%0, %1}, [%2];"
                         : "=l"(hx), "=l"(hy) : "r"(base + 36*4));
            FMA2(a1, q2[2*j], hx); FMA2(a1, q2[2*j+1], hy);
            asm volatile("ld.shared.v2.u64 {%0, %1}, [%2];"
                         : "=l"(hx), "=l"(hy) : "r"(base + 2*36*4));
            FMA2(a2, q2[2*j], hx); FMA2(a2, q2[2*j+1], hy);
            asm volatile("ld.shared.v2.u64 {%0, %1}, [%2];"
                         : "=l"(hx), "=l"(hy) : "r"(base + 3*36*4));
            FMA2(a3, q2[2*j], hx); FMA2(a3, q2[2*j+1], hy);
        }
        float4 o = make_float4((f2lo(a0)+f2hi(a0))*sc, (f2lo(a1)+f2hi(a1))*sc,
                               (f2lo(a2)+f2hi(a2))*sc, (f2lo(a3)+f2hi(a3))*sc);
        *(float4*)&S_s[ql4*LL + kt*64 + kg*4] = o;
    }
    __syncthreads();

    // ---- phase 2: bucketed softmax, THREAD per (ql,c) task, no reductions --
    // logits bounded (|s| ~ O(5)); plain sum-of-exp == softmax exactly.
    {
        int ql = tid >> 4, c = tid & 15;
        int q = qbase + ql;
        int off = off_s[c], cnt = cnt_s[c];
        float se = 0.f, sv = 0.f;
        for (int i = 0; i < cnt; i++) {
            int   kk = bidx_s[off + i];
            float lg = (kk <= q+1) ? fminf(S_s[ql*LL + kk], 80.f) : 0.f;
            float e  = __expf(lg);
            se += e;
            sv += e * val_s[kk];
        }
        x_s[ql*KK + c] = (cnt > 0) ? sv/se : 0.f;
    }
    __syncthreads();

    // ---- phase 3: GI[b,q,g] = cc[g] + sum_c M2[g][c] * x[q][c] ----
    #pragma unroll
    for (int i = 0; i < 12; i++) {
        int o = tid + i*512;               // 32*192 outputs
        int ql = o / GG, g = o - ql*GG;
        float acc = cc_s[g];
        #pragma unroll
        for (int c = 0; c < KK; c++) acc += M2_s[g*17+c] * x_s[ql*KK+c];
        g_GI[((size_t)(b*LL) + qbase + ql)*GG + g] = acc;
    }
}

// -------- kernel 3: GRU scan, one-barrier-per-step lane-pair design --------
__global__ void __launch_bounds__(128) k_gru2(const float* __restrict__ W_hh,
                                              float* __restrict__ out) {
    int b = blockIdx.x, tid = threadIdx.x;
    int u = tid >> 1, half = tid & 1;
    __shared__ __align__(16) float h_s[NHH];
    __shared__ __align__(16) float gi_s[2][CH*GG];

    // weights: rows u / 64+u / 128+u, k-slice [half*32, half*32+32), as f32x2
    unsigned long long wr[16], wz[16], wn[16];
    {
        const ulonglong2* r2 = (const ulonglong2*)(W_hh + (size_t)u*NHH       + half*32);
        const ulonglong2* z2 = (const ulonglong2*)(W_hh + (size_t)(64+u)*NHH  + half*32);
        const ulonglong2* n2 = (const ulonglong2*)(W_hh + (size_t)(128+u)*NHH + half*32);
        #pragma unroll
        for (int i = 0; i < 8; i++) {
            ulonglong2 a = r2[i]; wr[2*i] = a.x; wr[2*i+1] = a.y;
            ulonglong2 c = z2[i]; wz[2*i] = c.x; wz[2*i+1] = c.y;
            ulonglong2 d = n2[i]; wn[2*i] = d.x; wn[2*i+1] = d.y;
        }
    }
    float h_old = 0.f;
    if (tid < NHH) h_s[tid] = 0.f;

    unsigned haddr = (unsigned)__cvta_generic_to_shared(h_s) + half*128;
    unsigned gibase = (unsigned)__cvta_generic_to_shared(gi_s);
    const float* gi_src = g_GI + (size_t)b*LL*GG;
    float* out_b = out + (size_t)b*LL*NHH;

    // prologue: prefetch chunks 0 and 1
    #pragma unroll
    for (int cpre = 0; cpre < 2; cpre++) {
        #pragma unroll
        for (int i = 0; i < 6; i++) {
            int unit = tid + i*128;               // 768 x 16B per chunk
            asm volatile("cp.async.ca.shared.global [%0], [%1], 16;"
                :: "r"(gibase + cpre*(CH*GG*4) + unit*16),
                   "l"(gi_src + cpre*CH*GG + unit*4));
        }
        asm volatile("cp.async.commit_group;");
    }
    asm volatile("cp.async.wait_group 1;");
    __syncthreads();

    for (int c = 0; c < NCHUNK; c++) {
        const float* gi = gi_s[c & 1];
        for (int s = 0; s < CH; s++) {
            // gate inputs first (latency overlaps with matvec below)
            float gr = gi[s*GG + u], gz = gi[s*GG + 64 + u], gn = gi[s*GG + 128 + u];
            // half-matvec: 8x LDS.128 of h-half, 48 FMA2 over 6 chains
            unsigned long long ar0=0ull, ar1=0ull, az0=0ull, az1=0ull,
                               an0=0ull, an1=0ull;
            #pragma unroll
            for (int i = 0; i < 8; i++) {
                unsigned long long hx, hy;
                asm volatile("ld.shared.v2.u64 {%0, %1}, [%2];"
                             : "=l"(hx), "=l"(hy) : "r"(haddr + i*16));
                FMA2(ar0, wr[2*i], hx); FMA2(ar1, wr[2*i+1], hy);
                FMA2(az0, wz[2*i], hx); FMA2(az1, wz[2*i+1], hy);
                FMA2(an0, wn[2*i], hx); FMA2(an1, wn[2*i+1], hy);
            }
            float sr = (f2lo(ar0)+f2hi(ar0)) + (f2lo(ar1)+f2hi(ar1));
            float sz = (f2lo(az0)+f2hi(az0)) + (f2lo(az1)+f2hi(az1));
            float sn = (f2lo(an0)+f2hi(an0)) + (f2lo(an1)+f2hi(an1));
            sr += __shfl_xor_sync(0xffffffffu, sr, 1);
            sz += __shfl_xor_sync(0xffffffffu, sz, 1);
            sn += __shfl_xor_sync(0xffffffffu, sn, 1);

            float r = 0.5f * tanh_fast(0.5f * (gr + sr)) + 0.5f;  // sigmoid
            float z = 0.5f * tanh_fast(0.5f * (gz + sz)) + 0.5f;  // sigmoid
            float n = tanh_fast(gn + r*sn);
            float hnew = fmaf(z, h_old - n, n);      // (1-z)n + z*h
            if (half == 0) {
                h_s[u] = hnew;
                out_b[(c*CH + s)*NHH + u] = hnew;
            }
            h_old = hnew;
            __syncthreads();
        }
        // staged GI prefetch for chunk c+2 into the buffer just consumed
        if (c + 2 < NCHUNK) {
            #pragma unroll
            for (int i = 0; i < 6; i++) {
                int unit = tid + i*128;
                asm volatile("cp.async.ca.shared.global [%0], [%1], 16;"
                    :: "r"(gibase + (c & 1)*(CH*GG*4) + unit*16),
                       "l"(gi_src + (c+2)*CH*GG + unit*4));
            }
            asm volatile("cp.async.commit_group;");
            asm volatile("cp.async.wait_group 1;");   // chunk c+1 complete
        } else {
            asm volatile("cp.async.wait_group 0;");
        }
        __syncthreads();
    }
}

// -------- launch --------
extern "C" void kernel_launch(void* const* d_in, const int* in_sizes, int n_in,
                              void* d_out, int out_size) {
    const float* ts   = (const float*)d_in[0];
    const float* val  = (const float*)d_in[1];
    const int*   mark = (const int*)  d_in[2];
    const float* npm  = (const float*)d_in[3];
    const float* Wl   = (const float*)d_in[4];
    const float* bl   = (const float*)d_in[5];
    const float* Wp   = (const float*)d_in[6];
    const float* bp   = (const float*)d_in[7];
    const float* Wq   = (const float*)d_in[8];
    const float* bq   = (const float*)d_in[9];
    const float* Wk   = (const float*)d_in[10];
    const float* bk   = (const float*)d_in[11];
    const float* Wo   = (const float*)d_in[12];
    const float* bo   = (const float*)d_in[13];
    const float* W_ih = (const float*)d_in[14];
    const float* W_hh = (const float*)d_in[15];
    const float* b_ih = (const float*)d_in[16];
    const float* b_hh = (const float*)d_in[17];
    float* out = (float*)d_out;

    static int att_attr_set = 0;
    if (!att_attr_set) {
        cudaFuncSetAttribute(k_att2, cudaFuncAttributeMaxDynamicSharedMemorySize,
                             SMEM_ATT_BYTES);
        att_attr_set = 1;
    }

    k_setup<<<41, 512>>>(ts, Wl, bl, Wp, bp, Wq, bq, Wk, bk,
                         W_ih, Wo, b_ih, bo, b_hh, mark, npm);
    k_att2 <<<dim3(16,8), 512, SMEM_ATT_BYTES>>>(val);
    k_gru2 <<<8, 128>>>(W_hh, out);
}

// round 8
// speedup vs baseline: 1.1443x; 1.1443x over previous
#include <cuda_runtime.h>
#include <math.h>

#define BB  8
#define LL  512
#define KK  16
#define EE  32
#define NHH 64
#define GG  192
#define CH      16           // GRU: steps per GI prefetch chunk
#define NCHUNK  (LL/CH)      // 32

// -------- scratch (static device globals; no runtime allocation) --------
__device__ float g_q[BB*LL*EE];
__device__ float g_k[BB*LL*EE];
__device__ int   g_bcnt[BB*KK];
__device__ int   g_boff[BB*KK];
__device__ int   g_bidxC[BB*LL];     // compacted buckets, per-b 512 entries
__device__ float g_M2[GG*KK];        // W_ih @ Wo   (192 x 16)
__device__ float g_cc[GG];           // W_ih @ bo + b_ih
__device__ float g_GI[BB*LL*GG];     // precomputed input gates

__device__ __forceinline__ float tanh_fast(float x) {
    float y;
    asm("tanh.approx.f32 %0, %1;" : "=f"(y) : "f"(x));
    return y;
}
#define FMA2(acc, x, y) \
    asm("fma.rn.f32x2 %0, %1, %2, %0;" : "+l"(acc) : "l"(x), "l"(y))
__device__ __forceinline__ float f2lo(unsigned long long v) {
    return __uint_as_float((unsigned)v);
}
__device__ __forceinline__ float f2hi(unsigned long long v) {
    return __uint_as_float((unsigned)(v >> 32));
}

// -------- kernel 1: setup (proj blocks 0-63, fold 64, buckets 65-72) --------
__global__ void __launch_bounds__(512) k_setup(
        const float* __restrict__ ts,
        const float* __restrict__ Wl, const float* __restrict__ bl,
        const float* __restrict__ Wp, const float* __restrict__ bp,
        const float* __restrict__ Wq, const float* __restrict__ bq,
        const float* __restrict__ Wk, const float* __restrict__ bk,
        const float* __restrict__ W_ih, const float* __restrict__ Wo,
        const float* __restrict__ b_ih, const float* __restrict__ bo,
        const int*   __restrict__ mark, const float* __restrict__ npm) {
    int blk = blockIdx.x, tid = threadIdx.x;
    if (blk < 64) {
        // ---- projection: 64 rows per block ----
        __shared__ float ke_s[64*33];
        __shared__ float wq_s[EE*33], wk_s[EE*33];
        __shared__ float sWp[EE], sbp[EE];
        __shared__ float sWl, sbl;
        int b = blk >> 3, rbase = (blk & 7) * 64;

        for (int i = tid; i < EE*EE; i += 512) {
            int e = i >> 5, j = i & 31;
            wq_s[e*33+j] = Wq[i];
            wk_s[e*33+j] = Wk[i];
        }
        if (tid < EE-1) { sWp[tid] = Wp[tid]; sbp[tid] = bp[tid]; }
        if (tid == 0)   { sWl = Wl[0]; sbl = bl[0]; }
        __syncthreads();

        // phase A: key_emb for 64 rows (4 elems/thread)
        for (int idx = tid; idx < 64*EE; idx += 512) {
            int r = idx >> 5, i = idx & 31;
            float t = ts[b*LL + rbase + r];
            float v = (i == 0) ? fmaf(t, sWl, sbl)
                               : __sinf(fmaf(t, sWp[i-1], sbp[i-1]));
            ke_s[r*33 + i] = v;
        }
        __syncthreads();

        // phase B: thread (e = tid&31, warp w) does rows w*4..w*4+3
        int e = tid & 31, w = tid >> 5;
        float wq[EE], wk[EE];
        #pragma unroll
        for (int j = 0; j < EE; j++) { wq[j] = wq_s[e*33+j]; wk[j] = wk_s[e*33+j]; }
        float bqv = __ldg(&bq[e]), bkv = __ldg(&bk[e]);
        #pragma unroll
        for (int p = 0; p < 4; p++) {
            int r = w*4 + p;
            float aq = bqv, ak = bkv;
            #pragma unroll
            for (int j = 0; j < EE; j++) {
                float kv = ke_s[r*33+j];
                aq = fmaf(wq[j], kv, aq);
                ak = fmaf(wk[j], kv, ak);
            }
            int row = b*LL + rbase + r;
            g_q[row*EE + e] = aq;
            g_k[row*EE + e] = ak;
        }
    } else if (blk == 64) {
        // ---- fold: M2 = W_ih@Wo, cc = W_ih@bo + b_ih ----
        if (tid < GG) {
            int g = tid;
            float wrow[NHH];
            #pragma unroll
            for (int o = 0; o < NHH; o++) wrow[o] = W_ih[g*NHH+o];
            float cc = b_ih[g];
            #pragma unroll
            for (int o = 0; o < NHH; o++) cc += wrow[o] * bo[o];
            g_cc[g] = cc;
            for (int c = 0; c < KK; c++) {
                float a = 0.f;
                #pragma unroll
                for (int o = 0; o < NHH; o++) a += wrow[o] * Wo[o*KK+c];
                g_M2[g*KK+c] = a;
            }
        }
    } else {
        // ---- compacted bucket build: warp per category + block scan ----
        __shared__ int cnt_sh[KK], off_sh[KK];
        int b = blk - 65;
        int c = tid >> 5, lane = tid & 31;    // 16 warps = 16 categories
        unsigned mrec[LL/32];
        int cnt = 0;
        #pragma unroll
        for (int ch = 0; ch < LL/32; ch++) {
            int k = ch*32 + lane;
            int   mk = mark[b*LL+k];
            float np = npm[b*LL+k];
            bool hit = (mk == c+1) && (np > 0.f);
            unsigned m = __ballot_sync(0xffffffffu, hit);
            mrec[ch] = m;
            cnt += __popc(m);
        }
        if (lane == 0) cnt_sh[c] = cnt;
        __syncthreads();
        if (tid == 0) {
            int acc = 0;
            #pragma unroll
            for (int i = 0; i < KK; i++) { off_sh[i] = acc; acc += cnt_sh[i]; }
        }
        __syncthreads();
        int off = off_sh[c], pos = 0;
        #pragma unroll
        for (int ch = 0; ch < LL/32; ch++) {
            unsigned m = mrec[ch];
            if ((m >> lane) & 1u)
                g_bidxC[b*LL + off + pos + __popc(m & ((1u<<lane)-1u))] = ch*32 + lane;
            pos += __popc(m);
        }
        if (lane == 0) { g_bcnt[b*KK+c] = cnt; g_boff[b*KK+c] = off; }
    }
}

// -------- kernel 2: fused scores + bucketed softmax + GI --------
// smem layout (floats):
#define SOFF_S    0                       // 32*512 score tile
#define SOFF_KB   16384                   // 64*36  k staging (stride 36)
#define SOFF_VAL  (SOFF_KB+2304)          // 512
#define SOFF_X    (SOFF_VAL+512)          // 512
#define SOFF_M2   (SOFF_X+512)            // 192*17
#define SOFF_CC   (SOFF_M2+3264)          // 192
#define SOFF_INT  (SOFF_CC+192)           // ints: cnt 16, off 16, bidx 512
#define SMEM_ATT_BYTES ((SOFF_INT + 544) * 4)

__global__ void __launch_bounds__(512) k_att2(const float* __restrict__ val) {
    extern __shared__ float sm[];
    float* S_s   = sm + SOFF_S;
    float* kbuf  = sm + SOFF_KB;
    float* val_s = sm + SOFF_VAL;
    float* x_s   = sm + SOFF_X;
    float* M2_s  = sm + SOFF_M2;
    float* cc_s  = sm + SOFF_CC;
    int*   cnt_s  = (int*)(sm + SOFF_INT);
    int*   off_s  = cnt_s + KK;
    int*   bidx_s = off_s + KK;

    int tid = threadIdx.x;                 // 512 threads = 16 warps
    int b = blockIdx.y;
    int qbase = blockIdx.x * 32;

    if (tid < LL) {
        val_s[tid]  = val[b*LL+tid];
        bidx_s[tid] = g_bidxC[b*LL+tid];
    }
    if (tid < KK) { cnt_s[tid] = g_bcnt[b*KK+tid]; off_s[tid] = g_boff[b*KK+tid]; }
    for (int i = tid; i < GG*KK; i += 512) {
        int g = i >> 4, c = i & 15;
        M2_s[g*17+c] = g_M2[i];
    }
    if (tid < GG) cc_s[tid] = g_cc[tid];

    // ---- phase 1: S_tile[32][512] = q_tile @ k^T / sqrt(32) ----
    int ql4 = tid >> 4, kg = tid & 15;
    // q row in registers, packed f32x2 (16 x u64)
    unsigned long long q2[16];
    {
        const ulonglong2* qp = (const ulonglong2*)(g_q + (size_t)(b*LL + qbase + ql4)*EE);
        #pragma unroll
        for (int i = 0; i < 8; i++) {
            ulonglong2 v = qp[i];
            q2[2*i] = v.x; q2[2*i+1] = v.y;
        }
    }
    unsigned kaddr = (unsigned)__cvta_generic_to_shared(kbuf);
    const float sc = 0.17677669529663687f; // 1/sqrt(32)
    for (int kt = 0; kt < 8; kt++) {
        __syncthreads();
        {   // stage 64x32 k-block: one LDG.128 + STS.128 per thread
            int r = tid >> 3, e4 = (tid & 7) * 4;
            float4 v = *(const float4*)(g_k + (size_t)(b*LL + kt*64 + r)*EE + e4);
            *(float4*)&kbuf[r*36 + e4] = v;
        }
        __syncthreads();
        // rows kg, kg+16, kg+32, kg+48: an 8-lane phase reads 8 consecutive
        // rows at stride 36 floats -> bank starts 4*kg mod 32, conflict-free.
        unsigned long long a0=0ull, a1=0ull, a2=0ull, a3=0ull;
        unsigned rbase0 = kaddr + (unsigned)(kg*36*4);
        #pragma unroll
        for (int j = 0; j < 8; j++) {
            unsigned long long hx, hy;
            unsigned base = rbase0 + (unsigned)(j*16);
            asm volatile("ld.shared.v2.u64 {%0, %1}, [%2];"
                         : "=l"(hx), "=l"(hy) : "r"(base));
            FMA2(a0, q2[2*j], hx); FMA2(a0, q2[2*j+1], hy);
            asm volatile("ld.shared.v2.u64 {%0, %1}, [%2];"
                         : "=l"(hx), "=l"(hy) : "r"(base + 16*36*4));
            FMA2(a1, q2[2*j], hx); FMA2(a1, q2[2*j+1], hy);
            asm volatile("ld.shared.v2.u64 {%0, %1}, [%2];"
                         : "=l"(hx), "=l"(hy) : "r"(base + 32*36*4));
            FMA2(a2, q2[2*j], hx); FMA2(a2, q2[2*j+1], hy);
            asm volatile("ld.shared.v2.u64 {%0, %1}, [%2];"
                         : "=l"(hx), "=l"(hy) : "r"(base + 48*36*4));
            FMA2(a3, q2[2*j], hx); FMA2(a3, q2[2*j+1], hy);
        }
        float* so = &S_s[ql4*LL + kt*64 + kg];
        so[0]  = (f2lo(a0)+f2hi(a0))*sc;
        so[16] = (f2lo(a1)+f2hi(a1))*sc;
        so[32] = (f2lo(a2)+f2hi(a2))*sc;
        so[48] = (f2lo(a3)+f2hi(a3))*sc;
    }
    __syncthreads();

    // ---- phase 2: bucketed softmax, WARP per (ql,c) task, plain-sum ----
    // logits bounded (|s| small); sum-of-exp == softmax exactly; clamp@80
    // guards overflow without affecting results in-range.
    int wid = tid >> 5, lane = tid & 31;
    for (int task = wid; task < 32*KK; task += 16) {
        int ql = task >> 4, c = task & 15;
        int q = qbase + ql;
        int off = off_s[c], cnt = cnt_s[c];
        float se = 0.f, sv = 0.f;
        for (int i = lane; i < cnt; i += 32) {
            int   kk = bidx_s[off + i];
            float lg = (kk <= q+1) ? fminf(S_s[ql*LL + kk], 80.f) : 0.f;
            float e  = __expf(lg);
            se += e;
            sv += e * val_s[kk];
        }
        #pragma unroll
        for (int o = 16; o > 0; o >>= 1) {
            se += __shfl_xor_sync(0xffffffffu, se, o);
            sv += __shfl_xor_sync(0xffffffffu, sv, o);
        }
        if (lane == 0) x_s[ql*KK + c] = (cnt > 0) ? sv/se : 0.f;
    }
    __syncthreads();

    // ---- phase 3: GI[b,q,g] = cc[g] + sum_c M2[g][c] * x[q][c] ----
    for (int o = tid; o < 32*GG; o += 512) {
        int ql = o / GG, g = o - ql*GG;
        float acc = cc_s[g];
        #pragma unroll
        for (int c = 0; c < KK; c++) acc += M2_s[g*17+c] * x_s[ql*KK+c];
        g_GI[((size_t)(b*LL) + qbase + ql)*GG + g] = acc;
    }
}

// -------- kernel 3: GRU scan, one-barrier-per-step lane-pair design --------
__global__ void __launch_bounds__(128) k_gru2(const float* __restrict__ W_hh,
                                              const float* __restrict__ b_hh,
                                              float* __restrict__ out) {
    int b = blockIdx.x, tid = threadIdx.x;
    int u = tid >> 1, half = tid & 1;
    __shared__ __align__(16) float h_s[NHH];
    __shared__ __align__(16) float gi_s[2][CH*GG];

    // weights: rows u / 64+u / 128+u, k-slice [half*32, half*32+32), as f32x2
    unsigned long long wr[16], wz[16], wn[16];
    {
        const ulonglong2* r2 = (const ulonglong2*)(W_hh + (size_t)u*NHH       + half*32);
        const ulonglong2* z2 = (const ulonglong2*)(W_hh + (size_t)(64+u)*NHH  + half*32);
        const ulonglong2* n2 = (const ulonglong2*)(W_hh + (size_t)(128+u)*NHH + half*32);
        #pragma unroll
        for (int i = 0; i < 8; i++) {
            ulonglong2 a = r2[i]; wr[2*i] = a.x; wr[2*i+1] = a.y;
            ulonglong2 c = z2[i]; wz[2*i] = c.x; wz[2*i+1] = c.y;
            ulonglong2 d = n2[i]; wn[2*i] = d.x; wn[2*i+1] = d.y;
        }
    }
    float br = b_hh[u], bz = b_hh[64+u], bn = b_hh[128+u];
    float h_old = 0.f;
    if (tid < NHH) h_s[tid] = 0.f;

    unsigned haddr = (unsigned)__cvta_generic_to_shared(h_s) + half*128;
    unsigned gibase = (unsigned)__cvta_generic_to_shared(gi_s);
    const float* gi_src = g_GI + (size_t)b*LL*GG;
    float* out_b = out + (size_t)b*LL*NHH;

    // prologue: prefetch chunks 0 and 1
    #pragma unroll
    for (int cpre = 0; cpre < 2; cpre++) {
        #pragma unroll
        for (int i = 0; i < 6; i++) {
            int unit = tid + i*128;               // 768 x 16B per chunk
            asm volatile("cp.async.ca.shared.global [%0], [%1], 16;"
                :: "r"(gibase + cpre*(CH*GG*4) + unit*16),
                   "l"(gi_src + cpre*CH*GG + unit*4));
        }
        asm volatile("cp.async.commit_group;");
    }
    asm volatile("cp.async.wait_group 1;");
    __syncthreads();

    for (int c = 0; c < NCHUNK; c++) {
        const float* gi = gi_s[c & 1];
        for (int s = 0; s < CH; s++) {
            // gate inputs first (LDS latency overlaps with matvec)
            float gr = gi[s*GG + u], gz = gi[s*GG + 64 + u], gn = gi[s*GG + 128 + u];
            // half-matvec: 8x LDS.128 of h-half, 48 FMA2 over 6 chains
            unsigned long long ar0=0ull, ar1=0ull, az0=0ull, az1=0ull,
                               an0=0ull, an1=0ull;
            #pragma unroll
            for (int i = 0; i < 8; i++) {
                unsigned long long hx, hy;
                asm volatile("ld.shared.v2.u64 {%0, %1}, [%2];"
                             : "=l"(hx), "=l"(hy) : "r"(haddr + i*16));
                FMA2(ar0, wr[2*i], hx); FMA2(ar1, wr[2*i+1], hy);
                FMA2(az0, wz[2*i], hx); FMA2(az1, wz[2*i+1], hy);
                FMA2(an0, wn[2*i], hx); FMA2(an1, wn[2*i+1], hy);
            }
            float sr = (f2lo(ar0)+f2hi(ar0)) + (f2lo(ar1)+f2hi(ar1));
            float sz = (f2lo(az0)+f2hi(az0)) + (f2lo(az1)+f2hi(az1));
            float sn = (f2lo(an0)+f2hi(an0)) + (f2lo(an1)+f2hi(an1));
            sr += __shfl_xor_sync(0xffffffffu, sr, 1);
            sz += __shfl_xor_sync(0xffffffffu, sz, 1);
            sn += __shfl_xor_sync(0xffffffffu, sn, 1);

            float r = 0.5f * tanh_fast(0.5f * (gr + sr + br)) + 0.5f;  // sigmoid
            float z = 0.5f * tanh_fast(0.5f * (gz + sz + bz)) + 0.5f;  // sigmoid
            float n = tanh_fast(gn + r*(sn + bn));
            float hnew = fmaf(z, h_old - n, n);      // (1-z)n + z*h
            h_s[u] = hnew;                            // both halves, same value
            if (half == 0) out_b[(c*CH + s)*NHH + u] = hnew;
            h_old = hnew;
            __syncthreads();
        }
        // staged GI prefetch for chunk c+2 into the buffer just consumed
        if (c + 2 < NCHUNK) {
            #pragma unroll
            for (int i = 0; i < 6; i++) {
                int unit = tid + i*128;
                asm volatile("cp.async.ca.shared.global [%0], [%1], 16;"
                    :: "r"(gibase + (c & 1)*(CH*GG*4) + unit*16),
                       "l"(gi_src + (c+2)*CH*GG + unit*4));
            }
            asm volatile("cp.async.commit_group;");
            asm volatile("cp.async.wait_group 1;");   // chunk c+1 complete
        } else {
            asm volatile("cp.async.wait_group 0;");
        }
        __syncthreads();
    }
}

// -------- launch --------
extern "C" void kernel_launch(void* const* d_in, const int* in_sizes, int n_in,
                              void* d_out, int out_size) {
    const float* ts   = (const float*)d_in[0];
    const float* val  = (const float*)d_in[1];
    const int*   mark = (const int*)  d_in[2];
    const float* npm  = (const float*)d_in[3];
    const float* Wl   = (const float*)d_in[4];
    const float* bl   = (const float*)d_in[5];
    const float* Wp   = (const float*)d_in[6];
    const float* bp   = (const float*)d_in[7];
    const float* Wq   = (const float*)d_in[8];
    const float* bq   = (const float*)d_in[9];
    const float* Wk   = (const float*)d_in[10];
    const float* bk   = (const float*)d_in[11];
    const float* Wo   = (const float*)d_in[12];
    const float* bo   = (const float*)d_in[13];
    const float* W_ih = (const float*)d_in[14];
    const float* W_hh = (const float*)d_in[15];
    const float* b_ih = (const float*)d_in[16];
    const float* b_hh = (const float*)d_in[17];
    float* out = (float*)d_out;

    static int att_attr_set = 0;
    if (!att_attr_set) {
        cudaFuncSetAttribute(k_att2, cudaFuncAttributeMaxDynamicSharedMemorySize,
                             SMEM_ATT_BYTES);
        att_attr_set = 1;
    }

    k_setup<<<73, 512>>>(ts, Wl, bl, Wp, bp, Wq, bq, Wk, bk,
                         W_ih, Wo, b_ih, bo, mark, npm);
    k_att2 <<<dim3(16,8), 512, SMEM_ATT_BYTES>>>(val);
    k_gru2 <<<8, 128>>>(W_hh, b_hh, out);
}